// round 1
// baseline (speedup 1.0000x reference)
#include <cuda_runtime.h>
#include <math.h>

// Problem constants
#define B   32
#define C   512
#define HW  3136          // 56*56
#define HW4 784           // HW / 4 (float4)
#define HID 32            // C / RED
#define KSEL 256          // C / 2

// Allocation-free scratch (device globals)
__device__ float g_y[B * C];     // pooled mean+max per (b,c)
__device__ float g_map[B * C];   // final per-channel multiplier

// ---------------------------------------------------------------------------
// Kernel 1: per-(b,c) mean + max over 3136 spatial elements.
// One block per (b,c) row. 128 threads, float4 loads.
// ---------------------------------------------------------------------------
__global__ __launch_bounds__(128) void pool_kernel(const float* __restrict__ x) {
    const int bc = blockIdx.x;
    const float4* __restrict__ row =
        reinterpret_cast<const float4*>(x + (size_t)bc * HW);

    float s = 0.0f;
    float m = -INFINITY;
    for (int i = threadIdx.x; i < HW4; i += 128) {
        float4 v = row[i];
        s += (v.x + v.y) + (v.z + v.w);
        m = fmaxf(m, fmaxf(fmaxf(v.x, v.y), fmaxf(v.z, v.w)));
    }

    // warp reduce
    #pragma unroll
    for (int off = 16; off > 0; off >>= 1) {
        s += __shfl_xor_sync(0xFFFFFFFFu, s, off);
        m = fmaxf(m, __shfl_xor_sync(0xFFFFFFFFu, m, off));
    }

    __shared__ float ss[4], sm[4];
    const int wid = threadIdx.x >> 5;
    const int lid = threadIdx.x & 31;
    if (lid == 0) { ss[wid] = s; sm[wid] = m; }
    __syncthreads();
    if (threadIdx.x == 0) {
        float st = ss[0] + ss[1] + ss[2] + ss[3];
        float mt = fmaxf(fmaxf(sm[0], sm[1]), fmaxf(sm[2], sm[3]));
        g_y[bc] = st * (1.0f / (float)HW) + mt;
    }
}

// ---------------------------------------------------------------------------
// Kernel 2: tiny MLP + sigmoid + rank-mask + rand gate.
// One block per batch, 512 threads (one per channel).
// mask_t = (#{i : y2_i > y2_t} >= K)  <=>  y2_t < min(top_K)  (tie-correct)
// ---------------------------------------------------------------------------
__global__ __launch_bounds__(512) void mlp_mask_kernel(
    const float* __restrict__ w1, const float* __restrict__ b1,
    const float* __restrict__ prelu_a,
    const float* __restrict__ w2, const float* __restrict__ b2,
    const float* __restrict__ rand)
{
    const int b = blockIdx.x;
    const int t = threadIdx.x;
    const int wid = t >> 5;     // warp 0..15
    const int lid = t & 31;

    __shared__ float y_s[C];
    __shared__ float hpart[16][HID];   // per-warp partial sums for h
    __shared__ float h_s[HID];
    __shared__ float y2_s[C];

    y_s[t] = g_y[b * C + t];
    __syncthreads();

    // h partials: warp w covers channels [32w, 32w+32), lane j = hidden unit j.
    {
        float acc = 0.0f;
        const int c0 = wid * 32;
        #pragma unroll
        for (int k = 0; k < 32; k++) {
            const int c = c0 + k;
            acc = fmaf(y_s[c], __ldg(&w1[c * HID + lid]), acc);
        }
        hpart[wid][lid] = acc;
    }
    __syncthreads();

    // reduce the 16 partials + bias + PReLU (threads 0..31)
    if (t < HID) {
        float acc = b1[t];
        #pragma unroll
        for (int w = 0; w < 16; w++) acc += hpart[w][t];
        const float a = prelu_a[0];
        h_s[t] = (acc >= 0.0f) ? acc : a * acc;
    }
    __syncthreads();

    // y2[t] = sigmoid(h @ w2 + b2)
    float acc = __ldg(&b2[t]);
    #pragma unroll
    for (int j = 0; j < HID; j++)
        acc = fmaf(h_s[j], __ldg(&w2[j * C + t]), acc);
    const float y2 = 1.0f / (1.0f + expf(-acc));
    y2_s[t] = y2;
    __syncthreads();

    // rank count: number of strictly-greater elements
    int g = 0;
    #pragma unroll 8
    for (int i = 0; i < C; i++)
        g += (y2_s[i] > y2) ? 1 : 0;

    const bool below = (g >= KSEL);                    // y2 < k-th largest
    const bool rb = (__ldg(&rand[b * C + t]) - 0.5f < 0.0f);
    // final_map = rb ? (mask * y2) : y2
    const float fm = rb ? (below ? y2 : 0.0f) : y2;
    g_map[b * C + t] = fm;
}

// ---------------------------------------------------------------------------
// Kernel 3: out = x * final_map (broadcast over spatial).
// One block per (b,c) row, 256 threads, float4.
// ---------------------------------------------------------------------------
__global__ __launch_bounds__(256) void scale_kernel(
    const float* __restrict__ x, float* __restrict__ out)
{
    const int bc = blockIdx.x;
    const float f = g_map[bc];
    const float4* __restrict__ xi =
        reinterpret_cast<const float4*>(x + (size_t)bc * HW);
    float4* __restrict__ oo =
        reinterpret_cast<float4*>(out + (size_t)bc * HW);

    for (int i = threadIdx.x; i < HW4; i += 256) {
        float4 v = xi[i];
        v.x *= f; v.y *= f; v.z *= f; v.w *= f;
        oo[i] = v;
    }
}

// ---------------------------------------------------------------------------
// Launch. Inputs (metadata order): x, w1, b1, prelu_a, w2, b2, rand
// ---------------------------------------------------------------------------
extern "C" void kernel_launch(void* const* d_in, const int* in_sizes, int n_in,
                              void* d_out, int out_size) {
    const float* x       = (const float*)d_in[0];
    const float* w1      = (const float*)d_in[1];
    const float* b1      = (const float*)d_in[2];
    const float* prelu_a = (const float*)d_in[3];
    const float* w2      = (const float*)d_in[4];
    const float* b2      = (const float*)d_in[5];
    const float* rand    = (const float*)d_in[6];
    float* out = (float*)d_out;

    pool_kernel<<<B * C, 128>>>(x);
    mlp_mask_kernel<<<B, C>>>(w1, b1, prelu_a, w2, b2, rand);
    scale_kernel<<<B * C, 256>>>(x, out);
}

// round 2
// speedup vs baseline: 1.1164x; 1.1164x over previous
#include <cuda_runtime.h>
#include <math.h>

// Problem constants
#define B   32
#define C   512
#define HW  3136          // 56*56
#define HW4 784           // HW / 4 (float4)
#define HID 32            // C / RED
#define KSEL 256          // C / 2
#define NROW (B * C)      // 16384 rows

// Allocation-free scratch (device globals)
__device__ float g_y[NROW];     // pooled mean+max per (b,c)
__device__ float g_map[NROW];   // final per-channel multiplier

// ---------------------------------------------------------------------------
// Kernel 1: per-(b,c) mean + max over 3136 spatial elements.
// One WARP per row: no smem, no block sync, 4-wide independent float4 loads.
// 2048 blocks x 256 threads (8 warps/row-group).
// ---------------------------------------------------------------------------
__global__ __launch_bounds__(256) void pool_kernel(const float* __restrict__ x) {
    const int row = blockIdx.x * 8 + (threadIdx.x >> 5);
    const int lid = threadIdx.x & 31;
    const float4* __restrict__ r =
        reinterpret_cast<const float4*>(x + (size_t)row * HW);

    float s = 0.0f;
    float m = -INFINITY;

    int i = lid;
    // 6 unrolled groups of 4 independent loads (24 iters), then tail.
    #pragma unroll 1
    for (; i + 96 < HW4; i += 128) {
        float4 a = r[i];
        float4 b = r[i + 32];
        float4 c = r[i + 64];
        float4 d = r[i + 96];
        s += (a.x + a.y) + (a.z + a.w);
        s += (b.x + b.y) + (b.z + b.w);
        s += (c.x + c.y) + (c.z + c.w);
        s += (d.x + d.y) + (d.z + d.w);
        m = fmaxf(m, fmaxf(fmaxf(a.x, a.y), fmaxf(a.z, a.w)));
        m = fmaxf(m, fmaxf(fmaxf(b.x, b.y), fmaxf(b.z, b.w)));
        m = fmaxf(m, fmaxf(fmaxf(c.x, c.y), fmaxf(c.z, c.w)));
        m = fmaxf(m, fmaxf(fmaxf(d.x, d.y), fmaxf(d.z, d.w)));
    }
    for (; i < HW4; i += 32) {
        float4 a = r[i];
        s += (a.x + a.y) + (a.z + a.w);
        m = fmaxf(m, fmaxf(fmaxf(a.x, a.y), fmaxf(a.z, a.w)));
    }

    // warp reduce
    #pragma unroll
    for (int off = 16; off > 0; off >>= 1) {
        s += __shfl_xor_sync(0xFFFFFFFFu, s, off);
        m = fmaxf(m, __shfl_xor_sync(0xFFFFFFFFu, m, off));
    }
    if (lid == 0)
        g_y[row] = s * (1.0f / (float)HW) + m;
}

// ---------------------------------------------------------------------------
// Kernel 2: tiny MLP + sigmoid + rank-mask + rand gate.
// One block per batch, 512 threads (one per channel).
// mask_t = (#{i : y2_i > y2_t} >= K)  <=>  y2_t < min(top_K)  (tie-correct)
// ---------------------------------------------------------------------------
__global__ __launch_bounds__(512) void mlp_mask_kernel(
    const float* __restrict__ w1, const float* __restrict__ b1,
    const float* __restrict__ prelu_a,
    const float* __restrict__ w2, const float* __restrict__ b2,
    const float* __restrict__ rand)
{
    const int b = blockIdx.x;
    const int t = threadIdx.x;
    const int wid = t >> 5;     // warp 0..15
    const int lid = t & 31;

    __shared__ float y_s[C];
    __shared__ float hpart[16][HID];   // per-warp partial sums for h
    __shared__ float h_s[HID];
    __shared__ float y2_s[C];

    y_s[t] = g_y[b * C + t];
    __syncthreads();

    // h partials: warp w covers channels [32w, 32w+32), lane j = hidden unit j.
    {
        float acc = 0.0f;
        const int c0 = wid * 32;
        #pragma unroll
        for (int k = 0; k < 32; k++) {
            const int c = c0 + k;
            acc = fmaf(y_s[c], __ldg(&w1[c * HID + lid]), acc);
        }
        hpart[wid][lid] = acc;
    }
    __syncthreads();

    // reduce the 16 partials + bias + PReLU (threads 0..31)
    if (t < HID) {
        float acc = b1[t];
        #pragma unroll
        for (int w = 0; w < 16; w++) acc += hpart[w][t];
        const float a = prelu_a[0];
        h_s[t] = (acc >= 0.0f) ? acc : a * acc;
    }
    __syncthreads();

    // y2[t] = sigmoid(h @ w2 + b2)
    float acc = __ldg(&b2[t]);
    #pragma unroll
    for (int j = 0; j < HID; j++)
        acc = fmaf(h_s[j], __ldg(&w2[j * C + t]), acc);
    const float y2 = 1.0f / (1.0f + expf(-acc));
    y2_s[t] = y2;
    __syncthreads();

    // rank count: number of strictly-greater elements
    int g = 0;
    #pragma unroll 8
    for (int i = 0; i < C; i++)
        g += (y2_s[i] > y2) ? 1 : 0;

    const bool below = (g >= KSEL);                    // y2 < k-th largest
    const bool rb = (__ldg(&rand[b * C + t]) - 0.5f < 0.0f);
    // final_map = rb ? (mask * y2) : y2
    const float fm = rb ? (below ? y2 : 0.0f) : y2;
    g_map[b * C + t] = fm;
}

// ---------------------------------------------------------------------------
// Kernel 3: out = x * final_map (broadcast over spatial).
// Rows processed in DESCENDING order so the L2-resident tail of x (left over
// from pool_kernel's ascending scan) is read first -> L2 hits instead of DRAM.
// Streaming loads (.cs) + streaming stores (.cs) keep out-writes from
// evicting the x lines we want to reuse.
// ---------------------------------------------------------------------------
__global__ __launch_bounds__(256) void scale_kernel(
    const float* __restrict__ x, float* __restrict__ out)
{
    const int bc = (NROW - 1) - blockIdx.x;   // reversed
    const float f = g_map[bc];
    const float4* __restrict__ xi =
        reinterpret_cast<const float4*>(x + (size_t)bc * HW);
    float4* __restrict__ oo =
        reinterpret_cast<float4*>(out + (size_t)bc * HW);

    int i = threadIdx.x;
    // 784 = 3*256 + 16: 3 full iterations + tail
    #pragma unroll 1
    for (; i + 512 < HW4; i += 768) {
        float4 a = __ldcs(&xi[i]);
        float4 b = __ldcs(&xi[i + 256]);
        float4 c = __ldcs(&xi[i + 512]);
        a.x *= f; a.y *= f; a.z *= f; a.w *= f;
        b.x *= f; b.y *= f; b.z *= f; b.w *= f;
        c.x *= f; c.y *= f; c.z *= f; c.w *= f;
        __stcs(&oo[i], a);
        __stcs(&oo[i + 256], b);
        __stcs(&oo[i + 512], c);
    }
    for (; i < HW4; i += 256) {
        float4 a = __ldcs(&xi[i]);
        a.x *= f; a.y *= f; a.z *= f; a.w *= f;
        __stcs(&oo[i], a);
    }
}

// ---------------------------------------------------------------------------
// Launch. Inputs (metadata order): x, w1, b1, prelu_a, w2, b2, rand
// ---------------------------------------------------------------------------
extern "C" void kernel_launch(void* const* d_in, const int* in_sizes, int n_in,
                              void* d_out, int out_size) {
    const float* x       = (const float*)d_in[0];
    const float* w1      = (const float*)d_in[1];
    const float* b1      = (const float*)d_in[2];
    const float* prelu_a = (const float*)d_in[3];
    const float* w2      = (const float*)d_in[4];
    const float* b2      = (const float*)d_in[5];
    const float* rand    = (const float*)d_in[6];
    float* out = (float*)d_out;

    pool_kernel<<<NROW / 8, 256>>>(x);
    mlp_mask_kernel<<<B, C>>>(w1, b1, prelu_a, w2, b2, rand);
    scale_kernel<<<NROW, 256>>>(x, out);
}